// round 16
// baseline (speedup 1.0000x reference)
#include <cuda_runtime.h>
#include <cuda_fp16.h>
#include <cstdint>

// EnvironmentalAugmentations: pink = IIR(white, a=0.99, b=0.01); mixed = wave + 0.05*pink;
// out = mixed / max(|mixed|) if max > 1 else mixed.
//
// R16: resolve pass1/pass2 layout conflict with MINIMAL padding TP = align8(T) = T+4.
//  - Row byte-stride 220504*2 = 441008 is 16B-divisible -> every scratch row 16B
//    aligned -> pass1 keeps single aligned STG.128 (96us class; dense 2xSTG.64 wrote
//    half-sectors at 16B lane stride -> 110us class).
//  - pass2 = proven flat dense grid-stride (59us class) over the padded scratch:
//    only 1 pad uint2-group per row; ch = i4/TP4 (1 int div per 4 elems, hidden),
//    dst4 = i4 - ch (TP4 = T4+1), skip pad group. src reads fully contiguous.
// Predicted 156-168us (median ~160), rel_err ~2.09e-4.

#define A_COEF 0.99f
#define MIXC 0.0005f                 // NOISE_LEVEL * B_COEF = 0.05 * 0.01

constexpr int WARPS_PB = 8;          // warps per block (pass 1)
constexpr int U_ELEMS  = 8192;       // useful elements per warp tile
constexpr int WARM     = 256;        // warm-up elements (chunk > 0): 0.99^256=0.076
constexpr int GROUPS   = U_ELEMS / 256;
constexpr int WGROUPS  = WARM / 256;
constexpr int NCH      = 256;
constexpr int TP_CAP   = 221184;

__device__ __half g_scratch[(size_t)NCH * TP_CAP];  // fp16 mixed, rows padded to mult-8
__device__ float  g_bmax[4096];                     // per-block maxima

__global__ __launch_bounds__(WARPS_PB * 32)
void pink_mix_kernel(const float* __restrict__ wave,
                     const float* __restrict__ wn,
                     int T, int chunks, int TP)
{
    const int lane   = threadIdx.x & 31;
    const int warpId = threadIdx.x >> 5;
    const int wgid   = blockIdx.x * WARPS_PB + warpId;
    const int ch     = wgid / chunks;
    const int chunk  = wgid - ch * chunks;

    const float A1 = A_COEF;
    const float A2 = A1 * A1;
    const float A3 = A2 * A1;
    const float A4 = A2 * A2;
    const float A5 = A4 * A1;
    const float A6 = A4 * A2;
    const float A7 = A4 * A3;
    const float A8 = A4 * A4;
    const float A16 = A8 * A8;
    const float A32 = A16 * A16;
    const float A64 = A32 * A32;
    const float A128 = A64 * A64;
    const float A256 = A128 * A128;
    const float a8lane = powf(A8, (float)lane);   // a^(8*lane)

    float lmax = 0.0f;

    if (ch < NCH) {
        const long long rowf = (long long)ch * T;
        const float* __restrict__ wnr = wn   + rowf;
        const float* __restrict__ wvr = wave + rowf;
        __half*      __restrict__ scr = g_scratch + (long long)ch * TP;  // 16B-aligned row

        const int ustart = chunk * U_ELEMS;
        const int nWarm  = (chunk == 0) ? 0 : WGROUPS;
        int tg = (chunk == 0) ? 0 : (ustart - WARM);

        float Cc = 0.0f;  // carry: g-value at element (tg-1)   [pink = B_COEF * g]

        // ---- warm-up groups (256 elems each): g-scan only ----
        for (int g = 0; g < nWarm; ++g) {
            const int idx = tg + lane * 8;
            float4 wa = __ldcs(reinterpret_cast<const float4*>(wnr + idx));
            float4 wb = __ldcs(reinterpret_cast<const float4*>(wnr + idx + 4));
            float p0 = wa.x;
            float p1 = fmaf(A1, p0, wa.y);
            float p2 = fmaf(A1, p1, wa.z);
            float p3 = fmaf(A1, p2, wa.w);
            float p4 = fmaf(A1, p3, wb.x);
            float p5 = fmaf(A1, p4, wb.y);
            float p6 = fmaf(A1, p5, wb.z);
            float p7 = fmaf(A1, p6, wb.w);
            float tt = p7, u;
            u = __shfl_up_sync(0xffffffffu, tt, 1);  if (lane >= 1)  tt = fmaf(A8,   u, tt);
            u = __shfl_up_sync(0xffffffffu, tt, 2);  if (lane >= 2)  tt = fmaf(A16,  u, tt);
            u = __shfl_up_sync(0xffffffffu, tt, 4);  if (lane >= 4)  tt = fmaf(A32,  u, tt);
            u = __shfl_up_sync(0xffffffffu, tt, 8);  if (lane >= 8)  tt = fmaf(A64,  u, tt);
            u = __shfl_up_sync(0xffffffffu, tt, 16); if (lane >= 16) tt = fmaf(A128, u, tt);
            float T31 = __shfl_sync(0xffffffffu, tt, 31);
            Cc = fmaf(A256, Cc, T31);
            tg += 256;
        }

        // ---- useful groups: g-scan + mix + fp16 store + max ----
        for (int g = 0; g < GROUPS; ++g) {
            if (tg >= T) break;                      // warp-uniform
            const int idx = tg + lane * 8;
            const bool fullgrp = (tg + 256 <= T);

            float w0, w1, w2, w3, w4, w5, w6, w7;
            if (fullgrp) {
                float4 wa = __ldcs(reinterpret_cast<const float4*>(wnr + idx));
                float4 wb = __ldcs(reinterpret_cast<const float4*>(wnr + idx + 4));
                w0 = wa.x; w1 = wa.y; w2 = wa.z; w3 = wa.w;
                w4 = wb.x; w5 = wb.y; w6 = wb.z; w7 = wb.w;
            } else {
                w0 = (idx + 0 < T) ? wnr[idx + 0] : 0.0f;
                w1 = (idx + 1 < T) ? wnr[idx + 1] : 0.0f;
                w2 = (idx + 2 < T) ? wnr[idx + 2] : 0.0f;
                w3 = (idx + 3 < T) ? wnr[idx + 3] : 0.0f;
                w4 = (idx + 4 < T) ? wnr[idx + 4] : 0.0f;
                w5 = (idx + 5 < T) ? wnr[idx + 5] : 0.0f;
                w6 = (idx + 6 < T) ? wnr[idx + 6] : 0.0f;
                w7 = (idx + 7 < T) ? wnr[idx + 7] : 0.0f;
            }

            float p0 = w0;
            if (idx == 0) p0 = 100.0f * w0;          // pink[0]=w0 -> g0 = w0/B = 100*w0
            float p1 = fmaf(A1, p0, w1);
            float p2 = fmaf(A1, p1, w2);
            float p3 = fmaf(A1, p2, w3);
            float p4 = fmaf(A1, p3, w4);
            float p5 = fmaf(A1, p4, w5);
            float p6 = fmaf(A1, p5, w6);
            float p7 = fmaf(A1, p6, w7);

            float tt = p7, u;
            u = __shfl_up_sync(0xffffffffu, tt, 1);  if (lane >= 1)  tt = fmaf(A8,   u, tt);
            u = __shfl_up_sync(0xffffffffu, tt, 2);  if (lane >= 2)  tt = fmaf(A16,  u, tt);
            u = __shfl_up_sync(0xffffffffu, tt, 4);  if (lane >= 4)  tt = fmaf(A32,  u, tt);
            u = __shfl_up_sync(0xffffffffu, tt, 8);  if (lane >= 8)  tt = fmaf(A64,  u, tt);
            u = __shfl_up_sync(0xffffffffu, tt, 16); if (lane >= 16) tt = fmaf(A128, u, tt);

            float Tm1 = __shfl_up_sync(0xffffffffu, tt, 1);
            float cin = fmaf(a8lane, Cc, (lane ? Tm1 : 0.0f));

            float f0 = fmaf(A1, cin, p0);
            float f1 = fmaf(A2, cin, p1);
            float f2 = fmaf(A3, cin, p2);
            float f3 = fmaf(A4, cin, p3);
            float f4 = fmaf(A5, cin, p4);
            float f5 = fmaf(A6, cin, p5);
            float f6 = fmaf(A7, cin, p6);
            float f7 = fmaf(A8, cin, p7);

            float T31 = __shfl_sync(0xffffffffu, tt, 31);
            Cc = fmaf(A256, Cc, T31);

            if (fullgrp) {
                float4 va = __ldcs(reinterpret_cast<const float4*>(wvr + idx));
                float4 vb = __ldcs(reinterpret_cast<const float4*>(wvr + idx + 4));
                float o0 = fmaf(MIXC, f0, va.x);     // 0.05 * (B*g) + v
                float o1 = fmaf(MIXC, f1, va.y);
                float o2 = fmaf(MIXC, f2, va.z);
                float o3 = fmaf(MIXC, f3, va.w);
                float o4 = fmaf(MIXC, f4, vb.x);
                float o5 = fmaf(MIXC, f5, vb.y);
                float o6 = fmaf(MIXC, f6, vb.z);
                float o7 = fmaf(MIXC, f7, vb.w);
                __half2 h01 = __floats2half2_rn(o0, o1);
                __half2 h23 = __floats2half2_rn(o2, o3);
                __half2 h45 = __floats2half2_rn(o4, o5);
                __half2 h67 = __floats2half2_rn(o6, o7);
                uint4 pk;
                pk.x = *reinterpret_cast<unsigned*>(&h01);
                pk.y = *reinterpret_cast<unsigned*>(&h23);
                pk.z = *reinterpret_cast<unsigned*>(&h45);
                pk.w = *reinterpret_cast<unsigned*>(&h67);
                *reinterpret_cast<uint4*>(scr + idx) = pk;   // 16B aligned (TP mult of 8)
                lmax = fmaxf(lmax, fmaxf(fmaxf(fabsf(o0), fabsf(o1)),
                                         fmaxf(fabsf(o2), fabsf(o3))));
                lmax = fmaxf(lmax, fmaxf(fmaxf(fabsf(o4), fabsf(o5)),
                                         fmaxf(fabsf(o6), fabsf(o7))));
            } else {
                float fs[8] = {f0, f1, f2, f3, f4, f5, f6, f7};
                #pragma unroll
                for (int j = 0; j < 8; ++j) {
                    if (idx + j < T) {
                        float oo = fmaf(MIXC, fs[j], wvr[idx + j]);
                        scr[idx + j] = __float2half_rn(oo);
                        lmax = fmaxf(lmax, fabsf(oo));
                    }
                }
            }
            tg += 256;
        }
    }

    // ---- block max reduction -> g_bmax[blockIdx.x] ----
    #pragma unroll
    for (int o = 16; o; o >>= 1)
        lmax = fmaxf(lmax, __shfl_xor_sync(0xffffffffu, lmax, o));

    __shared__ float smax[WARPS_PB];
    if (lane == 0) smax[warpId] = lmax;
    __syncthreads();
    if (warpId == 0) {
        float m = (lane < WARPS_PB) ? smax[lane] : 0.0f;
        #pragma unroll
        for (int o = 4; o; o >>= 1)
            m = fmaxf(m, __shfl_xor_sync(0xffffffffu, m, o));
        if (lane == 0) g_bmax[blockIdx.x] = m;
    }
}

// Pass 2: flat grid-stride over the WHOLE padded scratch (dense contiguous reads).
// For group i4: ch = i4/TP4, r = i4 - ch*TP4; r == TP4-1 is the pad group (skip);
// otherwise dst4 = i4 - ch (since TP4 = T4+1). One int div per 4 elems, hidden.
__global__ __launch_bounds__(256)
void scale_expand_kernel(float* __restrict__ out, int TP4, int N4P, int nb)
{
    float m = 0.0f;
    for (int i = threadIdx.x; i < nb; i += 256)
        m = fmaxf(m, g_bmax[i]);
    #pragma unroll
    for (int o = 16; o; o >>= 1)
        m = fmaxf(m, __shfl_xor_sync(0xffffffffu, m, o));
    __shared__ float smax[8];
    if ((threadIdx.x & 31) == 0) smax[threadIdx.x >> 5] = m;
    __syncthreads();
    __shared__ float s_scale;
    if (threadIdx.x == 0) {
        float mm = smax[0];
        #pragma unroll
        for (int i = 1; i < 8; ++i) mm = fmaxf(mm, smax[i]);
        s_scale = (mm > 1.0f) ? (1.0f / mm) : 1.0f;
    }
    __syncthreads();
    const float s = s_scale;

    const uint2* __restrict__ src = reinterpret_cast<const uint2*>(g_scratch);
    float4* __restrict__ dst = reinterpret_cast<float4*>(out);

    for (int i = blockIdx.x * 256 + threadIdx.x; i < N4P; i += gridDim.x * 256) {
        uint2 pk = src[i];                       // contiguous read (incl. pad groups)
        const int ch = i / TP4;
        const int r  = i - ch * TP4;
        if (r == TP4 - 1) continue;              // pad group: 4 elems, discard
        __half2 h01 = *reinterpret_cast<__half2*>(&pk.x);
        __half2 h23 = *reinterpret_cast<__half2*>(&pk.y);
        float2 f01 = __half22float2(h01);
        float2 f23 = __half22float2(h23);
        float4 v;
        v.x = f01.x * s; v.y = f01.y * s;
        v.z = f23.x * s; v.w = f23.y * s;
        dst[i - ch] = v;                         // ch*T4 + r
    }
}

extern "C" void kernel_launch(void* const* d_in, const int* in_sizes, int n_in,
                              void* d_out, int out_size)
{
    const float* wave = (const float*)d_in[0];
    const float* wn   = (const float*)d_in[1];
    float* out = (float*)d_out;

    const int total  = in_sizes[0];
    const int T      = total / NCH;                       // 220500
    const int chunks = (T + U_ELEMS - 1) / U_ELEMS;       // 27
    const int nblk   = (NCH * chunks) / WARPS_PB;         // 864 blocks

    int TP = ((T + 7) / 8) * 8;                           // 220504: minimal pad, rows 16B-aligned
    if (TP > TP_CAP) TP = TP_CAP;
    const int TP4 = TP / 4;                               // 55126 = T/4 + 1
    const int N4P = NCH * TP4;                            // flat group count incl. pads

    pink_mix_kernel<<<nblk, WARPS_PB * 32>>>(wave, wn, T, chunks, TP);
    scale_expand_kernel<<<2048, 256>>>(out, TP4, N4P, nblk);
}

// round 17
// speedup vs baseline: 1.0666x; 1.0666x over previous
#include <cuda_runtime.h>
#include <cuda_fp16.h>
#include <cstdint>

// EnvironmentalAugmentations: pink = IIR(white, a=0.99, b=0.01); mixed = wave + 0.05*pink;
// out = mixed / max(|mixed|) if max > 1 else mixed.
//
// R17 = R12 (161.92us, reproduced twice) with pass2 ILP 4->8, KEEPING __ldcs/__stcs.
// Re-ranking on totals exposed that ncu's cache-flushed pass2 numbers don't transfer:
// in the real run scratch is L2-resident, and __stcs on the output stream (stops
// eviction of hot scratch) is the decisive factor (R9 dropped it -> 176; flat forms
// lacked it -> 170-172; R8/R12 kept it -> 161.9 twice). ILP8 should better exploit
// L2-hit latency (~250cyc) on the resident scratch read.
// Predicted 154-162us, rel_err ~2.09e-4.

#define A_COEF 0.99f
#define B_COEF 0.01f
#define NOISE_LEVEL 0.05f

constexpr int WARPS_PB = 8;          // warps per block (pass 1)
constexpr int U_ELEMS  = 8192;       // useful elements per warp tile
constexpr int WARM     = 256;        // warm-up elements (chunk > 0): 0.99^256=0.076
constexpr int GROUPS   = U_ELEMS / 256;
constexpr int WGROUPS  = WARM / 256;
constexpr int NCH      = 256;
constexpr int TP_MAX   = 221184;     // padded scratch row cap

__device__ __half g_scratch[(size_t)NCH * TP_MAX];  // fp16 mixed, padded rows
__device__ float  g_bmax[4096];                     // per-block maxima

__global__ __launch_bounds__(WARPS_PB * 32)
void pink_mix_kernel(const float* __restrict__ wave,
                     const float* __restrict__ wn,
                     int T, int chunks, int TP)
{
    const int lane   = threadIdx.x & 31;
    const int warpId = threadIdx.x >> 5;
    const int wgid   = blockIdx.x * WARPS_PB + warpId;
    const int ch     = wgid / chunks;
    const int chunk  = wgid - ch * chunks;

    const float A1 = A_COEF;
    const float A2 = A1 * A1;
    const float A3 = A2 * A1;
    const float A4 = A2 * A2;
    const float A5 = A4 * A1;
    const float A6 = A4 * A2;
    const float A7 = A4 * A3;
    const float A8 = A4 * A4;
    const float A16 = A8 * A8;
    const float A32 = A16 * A16;
    const float A64 = A32 * A32;
    const float A128 = A64 * A64;
    const float A256 = A128 * A128;
    const float a8lane = powf(A8, (float)lane);   // a^(8*lane)

    float lmax = 0.0f;

    if (ch < NCH) {
        const long long rowf = (long long)ch * T;
        const float* __restrict__ wnr = wn   + rowf;
        const float* __restrict__ wvr = wave + rowf;
        __half*      __restrict__ scr = g_scratch + (long long)ch * TP;

        const int ustart = chunk * U_ELEMS;
        const int nWarm  = (chunk == 0) ? 0 : WGROUPS;
        int tg = (chunk == 0) ? 0 : (ustart - WARM);

        float Cc = 0.0f;  // carry = pink value at element (tg-1)

        // ---- warm-up groups (256 elems each): scan only ----
        for (int g = 0; g < nWarm; ++g) {
            const int idx = tg + lane * 8;
            float4 wa = __ldcs(reinterpret_cast<const float4*>(wnr + idx));
            float4 wb = __ldcs(reinterpret_cast<const float4*>(wnr + idx + 4));
            float p0 = B_COEF * wa.x;
            float p1 = fmaf(A1, p0, B_COEF * wa.y);
            float p2 = fmaf(A1, p1, B_COEF * wa.z);
            float p3 = fmaf(A1, p2, B_COEF * wa.w);
            float p4 = fmaf(A1, p3, B_COEF * wb.x);
            float p5 = fmaf(A1, p4, B_COEF * wb.y);
            float p6 = fmaf(A1, p5, B_COEF * wb.z);
            float p7 = fmaf(A1, p6, B_COEF * wb.w);
            float tt = p7, u;
            u = __shfl_up_sync(0xffffffffu, tt, 1);  if (lane >= 1)  tt = fmaf(A8,   u, tt);
            u = __shfl_up_sync(0xffffffffu, tt, 2);  if (lane >= 2)  tt = fmaf(A16,  u, tt);
            u = __shfl_up_sync(0xffffffffu, tt, 4);  if (lane >= 4)  tt = fmaf(A32,  u, tt);
            u = __shfl_up_sync(0xffffffffu, tt, 8);  if (lane >= 8)  tt = fmaf(A64,  u, tt);
            u = __shfl_up_sync(0xffffffffu, tt, 16); if (lane >= 16) tt = fmaf(A128, u, tt);
            float T31 = __shfl_sync(0xffffffffu, tt, 31);
            Cc = fmaf(A256, Cc, T31);
            tg += 256;
        }

        // ---- useful groups: scan + mix + fp16 store + max ----
        for (int g = 0; g < GROUPS; ++g) {
            if (tg >= T) break;                      // warp-uniform
            const int idx = tg + lane * 8;
            const bool fullgrp = (tg + 256 <= T);

            float w0, w1, w2, w3, w4, w5, w6, w7;
            if (fullgrp) {
                float4 wa = __ldcs(reinterpret_cast<const float4*>(wnr + idx));
                float4 wb = __ldcs(reinterpret_cast<const float4*>(wnr + idx + 4));
                w0 = wa.x; w1 = wa.y; w2 = wa.z; w3 = wa.w;
                w4 = wb.x; w5 = wb.y; w6 = wb.z; w7 = wb.w;
            } else {
                w0 = (idx + 0 < T) ? wnr[idx + 0] : 0.0f;
                w1 = (idx + 1 < T) ? wnr[idx + 1] : 0.0f;
                w2 = (idx + 2 < T) ? wnr[idx + 2] : 0.0f;
                w3 = (idx + 3 < T) ? wnr[idx + 3] : 0.0f;
                w4 = (idx + 4 < T) ? wnr[idx + 4] : 0.0f;
                w5 = (idx + 5 < T) ? wnr[idx + 5] : 0.0f;
                w6 = (idx + 6 < T) ? wnr[idx + 6] : 0.0f;
                w7 = (idx + 7 < T) ? wnr[idx + 7] : 0.0f;
            }

            float g0 = B_COEF * w0;
            if (idx == 0) g0 = w0;                   // exact: pink[0] = w[0]
            float p0 = g0;
            float p1 = fmaf(A1, p0, B_COEF * w1);
            float p2 = fmaf(A1, p1, B_COEF * w2);
            float p3 = fmaf(A1, p2, B_COEF * w3);
            float p4 = fmaf(A1, p3, B_COEF * w4);
            float p5 = fmaf(A1, p4, B_COEF * w5);
            float p6 = fmaf(A1, p5, B_COEF * w6);
            float p7 = fmaf(A1, p6, B_COEF * w7);

            float tt = p7, u;
            u = __shfl_up_sync(0xffffffffu, tt, 1);  if (lane >= 1)  tt = fmaf(A8,   u, tt);
            u = __shfl_up_sync(0xffffffffu, tt, 2);  if (lane >= 2)  tt = fmaf(A16,  u, tt);
            u = __shfl_up_sync(0xffffffffu, tt, 4);  if (lane >= 4)  tt = fmaf(A32,  u, tt);
            u = __shfl_up_sync(0xffffffffu, tt, 8);  if (lane >= 8)  tt = fmaf(A64,  u, tt);
            u = __shfl_up_sync(0xffffffffu, tt, 16); if (lane >= 16) tt = fmaf(A128, u, tt);

            float Tm1 = __shfl_up_sync(0xffffffffu, tt, 1);
            float cin = fmaf(a8lane, Cc, (lane ? Tm1 : 0.0f));

            float f0 = fmaf(A1, cin, p0);
            float f1 = fmaf(A2, cin, p1);
            float f2 = fmaf(A3, cin, p2);
            float f3 = fmaf(A4, cin, p3);
            float f4 = fmaf(A5, cin, p4);
            float f5 = fmaf(A6, cin, p5);
            float f6 = fmaf(A7, cin, p6);
            float f7 = fmaf(A8, cin, p7);

            float T31 = __shfl_sync(0xffffffffu, tt, 31);
            Cc = fmaf(A256, Cc, T31);

            if (fullgrp) {
                float4 va = __ldcs(reinterpret_cast<const float4*>(wvr + idx));
                float4 vb = __ldcs(reinterpret_cast<const float4*>(wvr + idx + 4));
                float o0 = fmaf(NOISE_LEVEL, f0, va.x);
                float o1 = fmaf(NOISE_LEVEL, f1, va.y);
                float o2 = fmaf(NOISE_LEVEL, f2, va.z);
                float o3 = fmaf(NOISE_LEVEL, f3, va.w);
                float o4 = fmaf(NOISE_LEVEL, f4, vb.x);
                float o5 = fmaf(NOISE_LEVEL, f5, vb.y);
                float o6 = fmaf(NOISE_LEVEL, f6, vb.z);
                float o7 = fmaf(NOISE_LEVEL, f7, vb.w);
                __half2 h01 = __floats2half2_rn(o0, o1);
                __half2 h23 = __floats2half2_rn(o2, o3);
                __half2 h45 = __floats2half2_rn(o4, o5);
                __half2 h67 = __floats2half2_rn(o6, o7);
                uint4 pk;
                pk.x = *reinterpret_cast<unsigned*>(&h01);
                pk.y = *reinterpret_cast<unsigned*>(&h23);
                pk.z = *reinterpret_cast<unsigned*>(&h45);
                pk.w = *reinterpret_cast<unsigned*>(&h67);
                *reinterpret_cast<uint4*>(scr + idx) = pk;   // default policy: stay in L2
                lmax = fmaxf(lmax, fmaxf(fmaxf(fabsf(o0), fabsf(o1)),
                                         fmaxf(fabsf(o2), fabsf(o3))));
                lmax = fmaxf(lmax, fmaxf(fmaxf(fabsf(o4), fabsf(o5)),
                                         fmaxf(fabsf(o6), fabsf(o7))));
            } else {
                float fs[8] = {f0, f1, f2, f3, f4, f5, f6, f7};
                #pragma unroll
                for (int j = 0; j < 8; ++j) {
                    if (idx + j < T) {
                        float oo = fmaf(NOISE_LEVEL, fs[j], wvr[idx + j]);
                        scr[idx + j] = __float2half_rn(oo);
                        lmax = fmaxf(lmax, fabsf(oo));
                    }
                }
            }
            tg += 256;
        }
    }

    // ---- block max reduction -> g_bmax[blockIdx.x] ----
    #pragma unroll
    for (int o = 16; o; o >>= 1)
        lmax = fmaxf(lmax, __shfl_xor_sync(0xffffffffu, lmax, o));

    __shared__ float smax[WARPS_PB];
    if (lane == 0) smax[warpId] = lmax;
    __syncthreads();
    if (warpId == 0) {
        float m = (lane < WARPS_PB) ? smax[lane] : 0.0f;
        #pragma unroll
        for (int o = 4; o; o >>= 1)
            m = fmaxf(m, __shfl_xor_sync(0xffffffffu, m, o));
        if (lane == 0) g_bmax[blockIdx.x] = m;
    }
}

// Pass 2: reduce per-block maxima; expand fp16 scratch (padded rows) -> scaled fp32 out.
// R12's form with ILP 8: 4 floats/thread (uint2 __ldcs + __stcs float4), 8 slots/iter.
__global__ __launch_bounds__(256)
void scale_expand_kernel(float* __restrict__ out, int T, int TP, int PS, int nb)
{
    float m = 0.0f;
    for (int i = threadIdx.x; i < nb; i += 256)
        m = fmaxf(m, g_bmax[i]);
    #pragma unroll
    for (int o = 16; o; o >>= 1)
        m = fmaxf(m, __shfl_xor_sync(0xffffffffu, m, o));
    __shared__ float smax[8];
    if ((threadIdx.x & 31) == 0) smax[threadIdx.x >> 5] = m;
    __syncthreads();
    __shared__ float s_scale;
    if (threadIdx.x == 0) {
        float mm = smax[0];
        #pragma unroll
        for (int i = 1; i < 8; ++i) mm = fmaxf(mm, smax[i]);
        s_scale = (mm > 1.0f) ? (1.0f / mm) : 1.0f;
    }
    __syncthreads();
    const float s = s_scale;

    const int ch   = blockIdx.x >> 3;
    const int part = blockIdx.x & 7;
    const int start = part * PS;                 // PS mult of 8 -> 16B-aligned base
    const int end   = min(start + PS, T);
    if (start >= T) return;

    const __half* __restrict__ src = g_scratch + (long long)ch * TP;
    float*        __restrict__ dst = out       + (long long)ch * T;

    constexpr int STEP = 256 * 4;                // elems per slot (1024)

    auto do4 = [&](int t) {
        uint2 pk = __ldcs(reinterpret_cast<const uint2*>(src + t));
        __half2 h01 = *reinterpret_cast<__half2*>(&pk.x);
        __half2 h23 = *reinterpret_cast<__half2*>(&pk.y);
        float2 f01 = __half22float2(h01);
        float2 f23 = __half22float2(h23);
        float4 v;
        v.x = f01.x * s; v.y = f01.y * s; v.z = f23.x * s; v.w = f23.y * s;
        __stcs(reinterpret_cast<float4*>(dst + t), v);
    };

    int t = start + threadIdx.x * 4;
    // ILP=8 main loop: 8 independent slots per iteration (keeps __stcs!)
    for (; t + 7 * STEP + 4 <= end; t += 8 * STEP) {
        do4(t);
        do4(t + STEP);
        do4(t + 2 * STEP);
        do4(t + 3 * STEP);
        do4(t + 4 * STEP);
        do4(t + 5 * STEP);
        do4(t + 6 * STEP);
        do4(t + 7 * STEP);
    }
    // remainder slots
    for (; t + 4 <= end; t += STEP)
        do4(t);
    // scalar tail (< 4 elems at region end)
    {
        const int tfull = start + ((end - start) & ~3);
        const int rem   = end - tfull;
        if ((int)threadIdx.x < rem) {
            const int i = tfull + threadIdx.x;
            dst[i] = __half2float(src[i]) * s;
        }
    }
}

extern "C" void kernel_launch(void* const* d_in, const int* in_sizes, int n_in,
                              void* d_out, int out_size)
{
    const float* wave = (const float*)d_in[0];
    const float* wn   = (const float*)d_in[1];
    float* out = (float*)d_out;

    const int total  = in_sizes[0];
    const int T      = total / NCH;                       // 220500
    const int chunks = (T + U_ELEMS - 1) / U_ELEMS;       // 27
    const int nblk   = (NCH * chunks) / WARPS_PB;         // 864 blocks

    int TP = ((T + 127) / 128) * 128;                     // padded scratch row stride
    if (TP > TP_MAX) TP = TP_MAX;
    const int PS = (((T + 7) / 8) + 7) & ~7;              // per-part span, mult of 8

    pink_mix_kernel<<<nblk, WARPS_PB * 32>>>(wave, wn, T, chunks, TP);
    scale_expand_kernel<<<NCH * 8, 256>>>(out, T, TP, PS, nblk);
}